// round 1
// baseline (speedup 1.0000x reference)
#include <cuda_runtime.h>
#include <cuda_bf16.h>

#define NN 100000
#define EE 1600000
#define DD 64

// ---------------- scratch (device globals; no runtime allocation) ----------------
__device__ __align__(256) float g_bufA[NN * DD];
__device__ __align__(256) float g_bufB[NN * DD];
__device__ __align__(256) float g_agg [NN * DD];
__device__ int   g_cnt[NN];
__device__ int   g_rowptr[NN];
__device__ int   g_cursor[NN];
__device__ int   g_col[EE];
__device__ float g_deginv[NN];
__device__ int   g_blksum[128];
__device__ float g_t4[NN];
__device__ float g_u4[NN];
__device__ int   g_is64;

// ---------------- helpers ----------------
__device__ __forceinline__ long long edge_at(const void* ei, long long idx, int is64) {
    if (is64) return ((const long long*)ei)[idx];
    return (long long)((const int*)ei)[idx];
}

__device__ __forceinline__ unsigned long long splat2(float x) {
    unsigned long long d;
    asm("mov.b64 %0, {%1, %1};" : "=l"(d) : "f"(x));
    return d;
}
__device__ __forceinline__ unsigned long long fma2(unsigned long long a,
                                                   unsigned long long b,
                                                   unsigned long long c) {
    unsigned long long d;
    asm("fma.rn.f32x2 %0, %1, %2, %3;" : "=l"(d) : "l"(a), "l"(b), "l"(c));
    return d;
}
__device__ __forceinline__ void unpack2(unsigned long long v, float& lo, float& hi) {
    asm("mov.b64 {%0, %1}, %2;" : "=f"(lo), "=f"(hi) : "l"(v));
}

// ---------------- dtype detection: int64 vs int32 edge_index ----------------
__global__ void k_detect(const void* ei) {
    const unsigned* w = (const unsigned*)ei;
    int lane = threadIdx.x;
    bool allz = true;
    for (int i = lane; i < 1024; i += 32) allz &= (w[2 * i + 1] == 0u);
    allz = __all_sync(0xffffffffu, allz);
    if (lane == 0) g_is64 = allz ? 1 : 0;
}

// ---------------- CSR build ----------------
__global__ void k_hist(const void* ei) {
    int e = blockIdx.x * 256 + threadIdx.x;
    int is64 = g_is64;
    int d = (int)edge_at(ei, (long long)EE + e, is64);
    atomicAdd(&g_cnt[d], 1);
}

__global__ void k_scan_partial() {
    __shared__ int s[1024];
    int i = blockIdx.x * 1024 + threadIdx.x;
    int v = (i < NN) ? g_cnt[i] : 0;
    s[threadIdx.x] = v;
    __syncthreads();
    for (int off = 1; off < 1024; off <<= 1) {
        int x = (threadIdx.x >= off) ? s[threadIdx.x - off] : 0;
        __syncthreads();
        s[threadIdx.x] += x;
        __syncthreads();
    }
    if (i < NN) g_rowptr[i] = s[threadIdx.x] - v;  // exclusive
    if (threadIdx.x == 1023) g_blksum[blockIdx.x] = s[1023];
}

__global__ void k_scan_blk(int nb) {
    if (threadIdx.x == 0 && blockIdx.x == 0) {
        int run = 0;
        for (int b = 0; b < nb; b++) {
            int t = g_blksum[b];
            g_blksum[b] = run;
            run += t;
        }
    }
}

__global__ void k_scan_add() {
    int i = blockIdx.x * 1024 + threadIdx.x;
    if (i < NN) {
        int r = g_rowptr[i] + g_blksum[blockIdx.x];
        g_rowptr[i] = r;
        g_cursor[i] = r;
        int c = g_cnt[i];
        g_deginv[i] = 1.0f / (float)(c > 0 ? c : 1);
    }
}

__global__ void k_fill(const void* ei) {
    int e = blockIdx.x * 256 + threadIdx.x;
    int is64 = g_is64;
    int dn = (int)edge_at(ei, (long long)EE + e, is64);
    int sn = (int)edge_at(ei, (long long)e, is64);
    int pos = atomicAdd(&g_cursor[dn], 1);
    g_col[pos] = sn;
}

// ---------------- aggregation: a[r] = deginv[r] * sum_{nbr} h[nbr]  (64 floats/node) ----
// One warp per node; two 16-lane halves each handle one neighbor per iter (float4 per lane).
__global__ void k_agg(const float* __restrict__ h, float* __restrict__ a) {
    int node = blockIdx.x * 8 + (threadIdx.x >> 5);
    if (node >= NN) return;
    int lane = threadIdx.x & 31;
    int sub = lane >> 4;   // 0/1
    int tg  = lane & 15;   // feature group (float4)
    int start = g_rowptr[node];
    int cnt   = g_cnt[node];

    float4 acc = make_float4(0.f, 0.f, 0.f, 0.f);
    int j = sub;
    // unroll-by-2 to expose MLP
    for (; j + 2 < cnt; j += 4) {
        int c0 = g_col[start + j];
        int c1 = g_col[start + j + 2];
        float4 v0 = ((const float4*)(h + (size_t)c0 * DD))[tg];
        float4 v1 = ((const float4*)(h + (size_t)c1 * DD))[tg];
        acc.x += v0.x + v1.x; acc.y += v0.y + v1.y;
        acc.z += v0.z + v1.z; acc.w += v0.w + v1.w;
    }
    for (; j < cnt; j += 2) {
        int c0 = g_col[start + j];
        float4 v0 = ((const float4*)(h + (size_t)c0 * DD))[tg];
        acc.x += v0.x; acc.y += v0.y; acc.z += v0.z; acc.w += v0.w;
    }
    // combine the two halves
    acc.x += __shfl_down_sync(0xffffffffu, acc.x, 16);
    acc.y += __shfl_down_sync(0xffffffffu, acc.y, 16);
    acc.z += __shfl_down_sync(0xffffffffu, acc.z, 16);
    acc.w += __shfl_down_sync(0xffffffffu, acc.w, 16);
    if (sub == 0) {
        float di = g_deginv[node];
        float4 o = make_float4(acc.x * di, acc.y * di, acc.z * di, acc.w * di);
        ((float4*)(a + (size_t)node * DD))[tg] = o;
    }
}

// ---------------- fused GEMM: out = relu(h@Ws + a@Wn + b) ----------------
// block = 256 thr (8 warps) x 64 rows; warp handles 8 rows; lane owns cols {l, l+32};
// rows packed in pairs via fma.rn.f32x2 (FFMA2).
#define GEMM_SMEM_FLOATS (8192 + 64 + 8 * 1280)
__global__ __launch_bounds__(256) void k_gemm(
    const float* __restrict__ h, const float* __restrict__ a,
    const float* __restrict__ Ws, const float* __restrict__ Wn,
    const float* __restrict__ bias, float* __restrict__ out) {
    extern __shared__ float smem[];
    float* sW = smem;             // [2][64][64]
    float* sb = smem + 8192;      // [64]
    float* sst = smem + 8192 + 64;

    int t = threadIdx.x, w = t >> 5, lane = t & 31;

    for (int i = t; i < 8192; i += 256) sW[i] = (i < 4096) ? Ws[i] : Wn[i - 4096];
    if (t < 64) sb[t] = bias[t];
    __syncthreads();

    int rowbase = blockIdx.x * 64 + w * 8;
    float* sh = sst + w * 1280;   // [64][10] (padded stride 10)
    float* sa = sh + 640;

    // stage 8 rows of h and a, transposed: s[k][r]
#pragma unroll
    for (int r = 0; r < 8; r++) {
        int row = rowbase + r;
        float2 hv = make_float2(0.f, 0.f), av = make_float2(0.f, 0.f);
        if (row < NN) {
            hv = ((const float2*)(h + (size_t)row * DD))[lane];
            av = ((const float2*)(a + (size_t)row * DD))[lane];
        }
        sh[(2 * lane) * 10 + r]     = hv.x;
        sh[(2 * lane + 1) * 10 + r] = hv.y;
        sa[(2 * lane) * 10 + r]     = av.x;
        sa[(2 * lane + 1) * 10 + r] = av.y;
    }
    __syncwarp();

    unsigned long long acc[4][2];
#pragma unroll
    for (int rp = 0; rp < 4; rp++) { acc[rp][0] = 0ull; acc[rp][1] = 0ull; }

    const float* sWs = sW;
    const float* sWn = sW + 4096;
#pragma unroll 8
    for (int k = 0; k < 64; k++) {
        unsigned long long ws0 = splat2(sWs[k * 64 + lane]);
        unsigned long long ws1 = splat2(sWs[k * 64 + lane + 32]);
        unsigned long long wn0 = splat2(sWn[k * 64 + lane]);
        unsigned long long wn1 = splat2(sWn[k * 64 + lane + 32]);
#pragma unroll
        for (int rp = 0; rp < 4; rp++) {
            unsigned long long hp = *(const unsigned long long*)&sh[k * 10 + 2 * rp];
            unsigned long long ap = *(const unsigned long long*)&sa[k * 10 + 2 * rp];
            acc[rp][0] = fma2(hp, ws0, acc[rp][0]);
            acc[rp][0] = fma2(ap, wn0, acc[rp][0]);
            acc[rp][1] = fma2(hp, ws1, acc[rp][1]);
            acc[rp][1] = fma2(ap, wn1, acc[rp][1]);
        }
    }

    float b0 = sb[lane], b1 = sb[lane + 32];
#pragma unroll
    for (int rp = 0; rp < 4; rp++) {
        float lo0, hi0, lo1, hi1;
        unpack2(acc[rp][0], lo0, hi0);
        unpack2(acc[rp][1], lo1, hi1);
        int r0 = rowbase + 2 * rp, r1 = r0 + 1;
        if (r0 < NN) {
            float v0 = lo0 + b0; float v1 = lo1 + b1;
            out[(size_t)r0 * DD + lane]      = v0 > 0.f ? v0 : 0.f;
            out[(size_t)r0 * DD + lane + 32] = v1 > 0.f ? v1 : 0.f;
        }
        if (r1 < NN) {
            float v0 = hi0 + b0; float v1 = hi1 + b1;
            out[(size_t)r1 * DD + lane]      = v0 > 0.f ? v0 : 0.f;
            out[(size_t)r1 * DD + lane + 32] = v1 > 0.f ? v1 : 0.f;
        }
    }
}

// ---------------- layer 4: u = h@Ws4 + b4, t = h@Wn4 (scalar per node) ----------------
__global__ void k_lin4(const float* __restrict__ h, const float* __restrict__ ws,
                       const float* __restrict__ wn, const float* __restrict__ b) {
    __shared__ float sws[64], swn[64];
    int t = threadIdx.x;
    if (t < 64) { sws[t] = ws[t]; swn[t] = wn[t]; }
    __syncthreads();
    int node = blockIdx.x * 8 + (t >> 5);
    if (node >= NN) return;
    int lane = t & 31;
    const float* row = h + (size_t)node * DD;
    float x0 = row[lane], x1 = row[lane + 32];
    float u  = x0 * sws[lane] + x1 * sws[lane + 32];
    float tt = x0 * swn[lane] + x1 * swn[lane + 32];
#pragma unroll
    for (int o = 16; o; o >>= 1) {
        u  += __shfl_down_sync(0xffffffffu, u, o);
        tt += __shfl_down_sync(0xffffffffu, tt, o);
    }
    if (lane == 0) { g_u4[node] = u + b[0]; g_t4[node] = tt; }
}

__global__ void k_out4(float* __restrict__ out) {
    int node = blockIdx.x * 8 + (threadIdx.x >> 5);
    if (node >= NN) return;
    int lane = threadIdx.x & 31;
    int start = g_rowptr[node];
    int cnt   = g_cnt[node];
    float acc = 0.f;
    for (int j = lane; j < cnt; j += 32) acc += g_t4[g_col[start + j]];
#pragma unroll
    for (int o = 16; o; o >>= 1) acc += __shfl_down_sync(0xffffffffu, acc, o);
    if (lane == 0) {
        float z = g_u4[node] + g_deginv[node] * acc;
        out[node] = 1.0f / (1.0f + expf(-z));
    }
}

// ---------------- launch ----------------
extern "C" void kernel_launch(void* const* d_in, const int* in_sizes, int n_in,
                              void* d_out, int out_size) {
    const float* x   = (const float*)d_in[0];
    const void*  ei  = d_in[1];
    const float* Ws1 = (const float*)d_in[2];
    const float* Wn1 = (const float*)d_in[3];
    const float* b1  = (const float*)d_in[4];
    const float* Ws2 = (const float*)d_in[5];
    const float* Wn2 = (const float*)d_in[6];
    const float* b2  = (const float*)d_in[7];
    const float* Ws3 = (const float*)d_in[8];
    const float* Wn3 = (const float*)d_in[9];
    const float* b3  = (const float*)d_in[10];
    const float* Ws4 = (const float*)d_in[11];
    const float* Wn4 = (const float*)d_in[12];
    const float* b4  = (const float*)d_in[13];
    float* out = (float*)d_out;

    static float *pA = nullptr, *pB = nullptr, *pG = nullptr;
    static int* pcnt = nullptr;
    if (!pcnt) {
        void* p;
        cudaGetSymbolAddress(&p, g_cnt);  pcnt = (int*)p;
        cudaGetSymbolAddress(&p, g_bufA); pA = (float*)p;
        cudaGetSymbolAddress(&p, g_bufB); pB = (float*)p;
        cudaGetSymbolAddress(&p, g_agg);  pG = (float*)p;
        cudaFuncSetAttribute(k_gemm, cudaFuncAttributeMaxDynamicSharedMemorySize,
                             GEMM_SMEM_FLOATS * (int)sizeof(float));
    }

    const int nbScan = (NN + 1023) / 1024;       // 98
    const int gridE  = EE / 256;                 // 6250
    const int gridN8 = (NN + 7) / 8;             // 12500
    const int gridG  = (NN + 63) / 64;           // 1563
    const size_t smemG = GEMM_SMEM_FLOATS * sizeof(float);

    // CSR build
    k_detect<<<1, 32>>>(ei);
    cudaMemsetAsync(pcnt, 0, NN * sizeof(int));
    k_hist<<<gridE, 256>>>(ei);
    k_scan_partial<<<nbScan, 1024>>>();
    k_scan_blk<<<1, 32>>>(nbScan);
    k_scan_add<<<nbScan, 1024>>>();
    k_fill<<<gridE, 256>>>(ei);

    // layer 1: x -> A
    k_agg<<<gridN8, 256>>>(x, pG);
    k_gemm<<<gridG, 256, smemG>>>(x, pG, Ws1, Wn1, b1, pA);
    // layer 2: A -> B
    k_agg<<<gridN8, 256>>>(pA, pG);
    k_gemm<<<gridG, 256, smemG>>>(pA, pG, Ws2, Wn2, b2, pB);
    // layer 3: B -> A
    k_agg<<<gridN8, 256>>>(pB, pG);
    k_gemm<<<gridG, 256, smemG>>>(pB, pG, Ws3, Wn3, b3, pA);
    // layer 4: A -> out (transform-first, scalar aggregation)
    k_lin4<<<gridN8, 256>>>(pA, Ws4, Wn4, b4);
    k_out4<<<gridN8, 256>>>(out);
}

// round 2
// speedup vs baseline: 1.0338x; 1.0338x over previous
#include <cuda_runtime.h>
#include <cuda_fp16.h>
#include <cuda_bf16.h>

#define NN 100000
#define EE 1600000
#define DD 64

// ---------------- scratch (device globals; no runtime allocation) ----------------
__device__ __align__(256) float  g_bufA[NN * DD];
__device__ __align__(256) float  g_bufB[NN * DD];
__device__ __align__(256) float  g_agg [NN * DD];
__device__ __align__(256) __half g_h16a[NN * DD];
__device__ __align__(256) __half g_h16b[NN * DD];
__device__ int   g_cnt[NN];
__device__ int   g_rowptr[NN];
__device__ int   g_cursor[NN];
__device__ int   g_col[EE];
__device__ float g_deginv[NN];
__device__ int   g_blksum[128];
__device__ float g_t4[NN];
__device__ float g_u4[NN];
__device__ int   g_is64;

// ---------------- helpers ----------------
__device__ __forceinline__ long long edge_at(const void* ei, long long idx, int is64) {
    if (is64) return ((const long long*)ei)[idx];
    return (long long)((const int*)ei)[idx];
}

__device__ __forceinline__ unsigned long long splat2(float x) {
    unsigned long long d;
    asm("mov.b64 %0, {%1, %1};" : "=l"(d) : "f"(x));
    return d;
}
__device__ __forceinline__ unsigned long long fma2(unsigned long long a,
                                                   unsigned long long b,
                                                   unsigned long long c) {
    unsigned long long d;
    asm("fma.rn.f32x2 %0, %1, %2, %3;" : "=l"(d) : "l"(a), "l"(b), "l"(c));
    return d;
}
__device__ __forceinline__ void unpack2(unsigned long long v, float& lo, float& hi) {
    asm("mov.b64 {%0, %1}, %2;" : "=f"(lo), "=f"(hi) : "l"(v));
}

// ---------------- dtype detection: int64 vs int32 edge_index ----------------
__global__ void k_detect(const void* ei) {
    const unsigned* w = (const unsigned*)ei;
    int lane = threadIdx.x;
    bool allz = true;
    for (int i = lane; i < 1024; i += 32) allz &= (w[2 * i + 1] == 0u);
    allz = __all_sync(0xffffffffu, allz);
    if (lane == 0) g_is64 = allz ? 1 : 0;
}

// ---------------- x -> fp16 conversion ----------------
__global__ void k_conv(const float* __restrict__ x, __half* __restrict__ o) {
    int i = blockIdx.x * 256 + threadIdx.x;   // over NN*DD/4 float4s
    if (i >= NN * DD / 4) return;
    float4 v = ((const float4*)x)[i];
    __half2 a = __floats2half2_rn(v.x, v.y);
    __half2 b = __floats2half2_rn(v.z, v.w);
    ((__half2*)o)[2 * i]     = a;
    ((__half2*)o)[2 * i + 1] = b;
}

// ---------------- CSR build ----------------
__global__ void k_hist(const void* ei) {
    int e = blockIdx.x * 256 + threadIdx.x;
    int is64 = g_is64;
    int d = (int)edge_at(ei, (long long)EE + e, is64);
    atomicAdd(&g_cnt[d], 1);
}

__global__ void k_scan_partial() {
    __shared__ int s[1024];
    int i = blockIdx.x * 1024 + threadIdx.x;
    int v = (i < NN) ? g_cnt[i] : 0;
    s[threadIdx.x] = v;
    __syncthreads();
    for (int off = 1; off < 1024; off <<= 1) {
        int x = (threadIdx.x >= off) ? s[threadIdx.x - off] : 0;
        __syncthreads();
        s[threadIdx.x] += x;
        __syncthreads();
    }
    if (i < NN) g_rowptr[i] = s[threadIdx.x] - v;  // exclusive
    if (threadIdx.x == 1023) g_blksum[blockIdx.x] = s[1023];
}

// parallel exclusive scan of the (<=128) block sums in a single block
__global__ void k_scan_blk(int nb) {
    __shared__ int s[128];
    int t = threadIdx.x;
    int v = (t < nb) ? g_blksum[t] : 0;
    s[t] = v;
    __syncthreads();
    for (int off = 1; off < 128; off <<= 1) {
        int x = (t >= off) ? s[t - off] : 0;
        __syncthreads();
        s[t] += x;
        __syncthreads();
    }
    if (t < nb) g_blksum[t] = s[t] - v;  // exclusive
}

__global__ void k_scan_add() {
    int i = blockIdx.x * 1024 + threadIdx.x;
    if (i < NN) {
        int r = g_rowptr[i] + g_blksum[blockIdx.x];
        g_rowptr[i] = r;
        g_cursor[i] = r;
        int c = g_cnt[i];
        g_deginv[i] = 1.0f / (float)(c > 0 ? c : 1);
    }
}

__global__ void k_fill(const void* ei) {
    int e = blockIdx.x * 256 + threadIdx.x;
    int is64 = g_is64;
    int dn = (int)edge_at(ei, (long long)EE + e, is64);
    int sn = (int)edge_at(ei, (long long)e, is64);
    int pos = atomicAdd(&g_cursor[dn], 1);
    g_col[pos] = sn;
}

// ---------------- aggregation (fp16 gather, fp32 accumulate) ----------------
// One warp per node; each lane owns features {2l, 2l+1} (one half2 = 4B per row).
// A full row read = 32 lanes x 4B = 128B, perfectly coalesced.
__global__ void k_agg16(const __half* __restrict__ h, float* __restrict__ a) {
    int node = blockIdx.x * 8 + (threadIdx.x >> 5);
    if (node >= NN) return;
    int lane = threadIdx.x & 31;
    int start = g_rowptr[node];
    int cnt   = g_cnt[node];
    const int* __restrict__ col = g_col + start;

    float accx = 0.f, accy = 0.f;
    int j = 0;
    for (; j + 3 < cnt; j += 4) {
        int c0 = col[j], c1 = col[j + 1], c2 = col[j + 2], c3 = col[j + 3];
        __half2 v0 = ((const __half2*)(h + (size_t)c0 * DD))[lane];
        __half2 v1 = ((const __half2*)(h + (size_t)c1 * DD))[lane];
        __half2 v2 = ((const __half2*)(h + (size_t)c2 * DD))[lane];
        __half2 v3 = ((const __half2*)(h + (size_t)c3 * DD))[lane];
        float2 f0 = __half22float2(v0), f1 = __half22float2(v1);
        float2 f2 = __half22float2(v2), f3 = __half22float2(v3);
        accx += (f0.x + f1.x) + (f2.x + f3.x);
        accy += (f0.y + f1.y) + (f2.y + f3.y);
    }
    for (; j < cnt; j++) {
        __half2 v0 = ((const __half2*)(h + (size_t)col[j] * DD))[lane];
        float2 f0 = __half22float2(v0);
        accx += f0.x; accy += f0.y;
    }
    float di = g_deginv[node];
    ((float2*)(a + (size_t)node * DD))[lane] = make_float2(accx * di, accy * di);
}

// ---------------- fused GEMM: out = relu(h@Ws + a@Wn + b), plus fp16 copy ----------------
#define GEMM_SMEM_FLOATS (8192 + 64 + 8 * 1280)
__global__ __launch_bounds__(256) void k_gemm(
    const float* __restrict__ h, const float* __restrict__ a,
    const float* __restrict__ Ws, const float* __restrict__ Wn,
    const float* __restrict__ bias, float* __restrict__ out,
    __half* __restrict__ out16) {
    extern __shared__ float smem[];
    float* sW = smem;             // [2][64][64]
    float* sb = smem + 8192;      // [64]
    float* sst = smem + 8192 + 64;

    int t = threadIdx.x, w = t >> 5, lane = t & 31;

    for (int i = t; i < 8192; i += 256) sW[i] = (i < 4096) ? Ws[i] : Wn[i - 4096];
    if (t < 64) sb[t] = bias[t];
    __syncthreads();

    int rowbase = blockIdx.x * 64 + w * 8;
    float* sh = sst + w * 1280;   // [64][10] (padded stride 10)
    float* sa = sh + 640;

#pragma unroll
    for (int r = 0; r < 8; r++) {
        int row = rowbase + r;
        float2 hv = make_float2(0.f, 0.f), av = make_float2(0.f, 0.f);
        if (row < NN) {
            hv = ((const float2*)(h + (size_t)row * DD))[lane];
            av = ((const float2*)(a + (size_t)row * DD))[lane];
        }
        sh[(2 * lane) * 10 + r]     = hv.x;
        sh[(2 * lane + 1) * 10 + r] = hv.y;
        sa[(2 * lane) * 10 + r]     = av.x;
        sa[(2 * lane + 1) * 10 + r] = av.y;
    }
    __syncwarp();

    unsigned long long acc[4][2];
#pragma unroll
    for (int rp = 0; rp < 4; rp++) { acc[rp][0] = 0ull; acc[rp][1] = 0ull; }

    const float* sWs = sW;
    const float* sWn = sW + 4096;
#pragma unroll 8
    for (int k = 0; k < 64; k++) {
        unsigned long long ws0 = splat2(sWs[k * 64 + lane]);
        unsigned long long ws1 = splat2(sWs[k * 64 + lane + 32]);
        unsigned long long wn0 = splat2(sWn[k * 64 + lane]);
        unsigned long long wn1 = splat2(sWn[k * 64 + lane + 32]);
#pragma unroll
        for (int rp = 0; rp < 4; rp++) {
            unsigned long long hp = *(const unsigned long long*)&sh[k * 10 + 2 * rp];
            unsigned long long ap = *(const unsigned long long*)&sa[k * 10 + 2 * rp];
            acc[rp][0] = fma2(hp, ws0, acc[rp][0]);
            acc[rp][0] = fma2(ap, wn0, acc[rp][0]);
            acc[rp][1] = fma2(hp, ws1, acc[rp][1]);
            acc[rp][1] = fma2(ap, wn1, acc[rp][1]);
        }
    }

    float b0 = sb[lane], b1 = sb[lane + 32];
#pragma unroll
    for (int rp = 0; rp < 4; rp++) {
        float lo0, hi0, lo1, hi1;
        unpack2(acc[rp][0], lo0, hi0);
        unpack2(acc[rp][1], lo1, hi1);
        int r0 = rowbase + 2 * rp, r1 = r0 + 1;
        if (r0 < NN) {
            float v0 = lo0 + b0; float v1 = lo1 + b1;
            v0 = v0 > 0.f ? v0 : 0.f;
            v1 = v1 > 0.f ? v1 : 0.f;
            out[(size_t)r0 * DD + lane]      = v0;
            out[(size_t)r0 * DD + lane + 32] = v1;
            if (out16) {
                out16[(size_t)r0 * DD + lane]      = __float2half_rn(v0);
                out16[(size_t)r0 * DD + lane + 32] = __float2half_rn(v1);
            }
        }
        if (r1 < NN) {
            float v0 = hi0 + b0; float v1 = hi1 + b1;
            v0 = v0 > 0.f ? v0 : 0.f;
            v1 = v1 > 0.f ? v1 : 0.f;
            out[(size_t)r1 * DD + lane]      = v0;
            out[(size_t)r1 * DD + lane + 32] = v1;
            if (out16) {
                out16[(size_t)r1 * DD + lane]      = __float2half_rn(v0);
                out16[(size_t)r1 * DD + lane + 32] = __float2half_rn(v1);
            }
        }
    }
}

// ---------------- layer 4: u = h@Ws4 + b4, t = h@Wn4 (scalar per node) ----------------
__global__ void k_lin4(const float* __restrict__ h, const float* __restrict__ ws,
                       const float* __restrict__ wn, const float* __restrict__ b) {
    __shared__ float sws[64], swn[64];
    int t = threadIdx.x;
    if (t < 64) { sws[t] = ws[t]; swn[t] = wn[t]; }
    __syncthreads();
    int node = blockIdx.x * 8 + (t >> 5);
    if (node >= NN) return;
    int lane = t & 31;
    const float* row = h + (size_t)node * DD;
    float x0 = row[lane], x1 = row[lane + 32];
    float u  = x0 * sws[lane] + x1 * sws[lane + 32];
    float tt = x0 * swn[lane] + x1 * swn[lane + 32];
#pragma unroll
    for (int o = 16; o; o >>= 1) {
        u  += __shfl_down_sync(0xffffffffu, u, o);
        tt += __shfl_down_sync(0xffffffffu, tt, o);
    }
    if (lane == 0) { g_u4[node] = u + b[0]; g_t4[node] = tt; }
}

__global__ void k_out4(float* __restrict__ out) {
    int node = blockIdx.x * 8 + (threadIdx.x >> 5);
    if (node >= NN) return;
    int lane = threadIdx.x & 31;
    int start = g_rowptr[node];
    int cnt   = g_cnt[node];
    float acc = 0.f;
    for (int j = lane; j < cnt; j += 32) acc += g_t4[g_col[start + j]];
#pragma unroll
    for (int o = 16; o; o >>= 1) acc += __shfl_down_sync(0xffffffffu, acc, o);
    if (lane == 0) {
        float z = g_u4[node] + g_deginv[node] * acc;
        out[node] = 1.0f / (1.0f + expf(-z));
    }
}

// ---------------- launch ----------------
extern "C" void kernel_launch(void* const* d_in, const int* in_sizes, int n_in,
                              void* d_out, int out_size) {
    const float* x   = (const float*)d_in[0];
    const void*  ei  = d_in[1];
    const float* Ws1 = (const float*)d_in[2];
    const float* Wn1 = (const float*)d_in[3];
    const float* b1  = (const float*)d_in[4];
    const float* Ws2 = (const float*)d_in[5];
    const float* Wn2 = (const float*)d_in[6];
    const float* b2  = (const float*)d_in[7];
    const float* Ws3 = (const float*)d_in[8];
    const float* Wn3 = (const float*)d_in[9];
    const float* b3  = (const float*)d_in[10];
    const float* Ws4 = (const float*)d_in[11];
    const float* Wn4 = (const float*)d_in[12];
    const float* b4  = (const float*)d_in[13];
    float* out = (float*)d_out;

    static float *pA = nullptr, *pB = nullptr, *pG = nullptr;
    static __half *pHa = nullptr, *pHb = nullptr;
    static int* pcnt = nullptr;
    if (!pcnt) {
        void* p;
        cudaGetSymbolAddress(&p, g_cnt);   pcnt = (int*)p;
        cudaGetSymbolAddress(&p, g_bufA);  pA  = (float*)p;
        cudaGetSymbolAddress(&p, g_bufB);  pB  = (float*)p;
        cudaGetSymbolAddress(&p, g_agg);   pG  = (float*)p;
        cudaGetSymbolAddress(&p, g_h16a);  pHa = (__half*)p;
        cudaGetSymbolAddress(&p, g_h16b);  pHb = (__half*)p;
        cudaFuncSetAttribute(k_gemm, cudaFuncAttributeMaxDynamicSharedMemorySize,
                             GEMM_SMEM_FLOATS * (int)sizeof(float));
    }

    const int nbScan = (NN + 1023) / 1024;       // 98
    const int gridE  = EE / 256;                 // 6250
    const int gridN8 = (NN + 7) / 8;             // 12500
    const int gridG  = (NN + 63) / 64;           // 1563
    const int gridC  = (NN * DD / 4 + 255) / 256;
    const size_t smemG = GEMM_SMEM_FLOATS * sizeof(float);

    // CSR build + x conversion
    k_detect<<<1, 32>>>(ei);
    cudaMemsetAsync(pcnt, 0, NN * sizeof(int));
    k_conv<<<gridC, 256>>>(x, pHa);
    k_hist<<<gridE, 256>>>(ei);
    k_scan_partial<<<nbScan, 1024>>>();
    k_scan_blk<<<1, 128>>>(nbScan);
    k_scan_add<<<nbScan, 1024>>>();
    k_fill<<<gridE, 256>>>(ei);

    // layer 1: x -> A (fp16 copy of A in pHb)
    k_agg16<<<gridN8, 256>>>(pHa, pG);
    k_gemm<<<gridG, 256, smemG>>>(x, pG, Ws1, Wn1, b1, pA, pHb);
    // layer 2: A -> B (fp16 copy in pHa)
    k_agg16<<<gridN8, 256>>>(pHb, pG);
    k_gemm<<<gridG, 256, smemG>>>(pA, pG, Ws2, Wn2, b2, pB, pHa);
    // layer 3: B -> A (no fp16 copy needed)
    k_agg16<<<gridN8, 256>>>(pHa, pG);
    k_gemm<<<gridG, 256, smemG>>>(pB, pG, Ws3, Wn3, b3, pA, ((__half*)0));
    // layer 4: A -> out (transform-first, scalar aggregation)
    k_lin4<<<gridN8, 256>>>(pA, Ws4, Wn4, b4);
    k_out4<<<gridN8, 256>>>(out);
}